// round 4
// baseline (speedup 1.0000x reference)
#include <cuda_runtime.h>
#include <cuda_bf16.h>
#include <cstdint>

// Problem constants
#define BB   4
#define SS   2048
#define DD   1024
#define HH   16
#define DKK  64
#define MM   (BB*SS)          // 8192 rows

// -------- scratch (device globals: no allocation allowed) --------
__device__ float g_qbuf[MM*DD];
__device__ float g_kbuf[MM*DD];
__device__ float g_vbuf[MM*DD];
__device__ float g_abuf[MM*DD];

// -------- helpers --------
__device__ __forceinline__ uint32_t f2tf(float x) {
    uint32_t r;
    asm("cvt.rna.tf32.f32 %0, %1;" : "=r"(r) : "f"(x));
    return r;
}

__device__ __forceinline__ void mma8(float* c, const uint32_t* a, const uint32_t* b) {
    asm volatile(
        "mma.sync.aligned.m16n8k8.row.col.f32.tf32.tf32.f32 "
        "{%0,%1,%2,%3}, {%4,%5,%6,%7}, {%8,%9}, {%0,%1,%2,%3};"
        : "+f"(c[0]), "+f"(c[1]), "+f"(c[2]), "+f"(c[3])
        : "r"(a[0]), "r"(a[1]), "r"(a[2]), "r"(a[3]), "r"(b[0]), "r"(b[1]));
}

__device__ __forceinline__ void cp16(void* s, const void* g) {
    uint32_t sa = (uint32_t)__cvta_generic_to_shared(s);
    asm volatile("cp.async.cg.shared.global [%0], [%1], 16;" :: "r"(sa), "l"(g));
}

// ============================================================================
// TF32 GEMM: C[M,N] = A[M,K] * B[N,K]^T   (both operands K-contiguous)
// Block 128x128, K-tile 32, 256 threads (8 warps, 2x4, warp tile 64x32)
// ============================================================================
#define TSTR 36   // smem row stride (floats): 128B-aligned-ish, conflict-free frag reads

__global__ void __launch_bounds__(256) gemm_tf32(
    const float* __restrict__ A, const float* __restrict__ Bw,
    float* __restrict__ C, int M, int N, int K)
{
    extern __shared__ float sm[];
    float* As = sm;                    // [2][128][TSTR]
    float* Bs = sm + 2 * 128 * TSTR;   // [2][128][TSTR]

    const int tid  = threadIdx.x;
    const int warp = tid >> 5, lane = tid & 31;
    const int wm = (warp >> 2) * 64;   // 0 / 64
    const int wn = (warp & 3) * 32;    // 0..96
    const int g  = lane >> 2, tg = lane & 3;
    const int bm = blockIdx.y * 128, bn = blockIdx.x * 128;

    const float* Ag = A  + bm * K;
    const float* Bg = Bw + bn * K;

    float acc[4][4][4];
    #pragma unroll
    for (int mi = 0; mi < 4; mi++)
        #pragma unroll
        for (int ni = 0; ni < 4; ni++)
            #pragma unroll
            for (int r = 0; r < 4; r++) acc[mi][ni][r] = 0.f;

    const int KT = K >> 5;

    // prologue: stage tile 0
    {
        #pragma unroll
        for (int i = 0; i < 4; i++) {
            int idx = tid + (i << 8);
            int r = idx >> 3, c = (idx & 7) << 2;
            cp16(As + r * TSTR + c, Ag + r * K + c);
            cp16(Bs + r * TSTR + c, Bg + r * K + c);
        }
        asm volatile("cp.async.commit_group;");
    }

    for (int kt = 0; kt < KT; kt++) {
        asm volatile("cp.async.wait_group 0;");
        __syncthreads();

        if (kt + 1 < KT) {
            float* as = As + ((kt + 1) & 1) * 128 * TSTR;
            float* bs = Bs + ((kt + 1) & 1) * 128 * TSTR;
            const int kk = (kt + 1) << 5;
            #pragma unroll
            for (int i = 0; i < 4; i++) {
                int idx = tid + (i << 8);
                int r = idx >> 3, c = (idx & 7) << 2;
                cp16(as + r * TSTR + c, Ag + r * K + kk + c);
                cp16(bs + r * TSTR + c, Bg + r * K + kk + c);
            }
            asm volatile("cp.async.commit_group;");
        }

        const float* as = As + (kt & 1) * 128 * TSTR;
        const float* bs = Bs + (kt & 1) * 128 * TSTR;

        #pragma unroll
        for (int k8 = 0; k8 < 4; k8++) {
            uint32_t af[4][4], bf[4][2];
            const int kc = (k8 << 3) + tg;
            #pragma unroll
            for (int mi = 0; mi < 4; mi++) {
                int r0 = wm + mi * 16 + g;
                af[mi][0] = f2tf(as[r0 * TSTR + kc]);
                af[mi][1] = f2tf(as[(r0 + 8) * TSTR + kc]);
                af[mi][2] = f2tf(as[r0 * TSTR + kc + 4]);
                af[mi][3] = f2tf(as[(r0 + 8) * TSTR + kc + 4]);
            }
            #pragma unroll
            for (int ni = 0; ni < 4; ni++) {
                int n0 = wn + ni * 8 + g;
                bf[ni][0] = f2tf(bs[n0 * TSTR + kc]);
                bf[ni][1] = f2tf(bs[n0 * TSTR + kc + 4]);
            }
            #pragma unroll
            for (int mi = 0; mi < 4; mi++)
                #pragma unroll
                for (int ni = 0; ni < 4; ni++)
                    mma8(acc[mi][ni], af[mi], bf[ni]);
        }
    }

    // epilogue
    #pragma unroll
    for (int mi = 0; mi < 4; mi++) {
        int row = bm + wm + mi * 16 + g;
        #pragma unroll
        for (int ni = 0; ni < 4; ni++) {
            int col = bn + wn + ni * 8 + (tg << 1);
            *(float2*)&C[row * N + col]       = make_float2(acc[mi][ni][0], acc[mi][ni][1]);
            *(float2*)&C[(row + 8) * N + col] = make_float2(acc[mi][ni][2], acc[mi][ni][3]);
        }
    }
}

// ============================================================================
// Causal flash attention.
// Block: one (b, h, 128-row Q tile). 256 threads, 8 warps; warp owns 16 Q rows.
// QK^T and P*V via tf32 mma. Online softmax with quad-shuffle row reductions.
// ============================================================================
#define QSTR 68   // smem row stride (floats)

__global__ void __launch_bounds__(256) attn_kernel(
    const float* __restrict__ Q, const float* __restrict__ Kb,
    const float* __restrict__ Vb, float* __restrict__ O)
{
    extern __shared__ float sm[];
    float* Qs = sm;                   // 128 x QSTR
    float* Ks = Qs + 128 * QSTR;      // 64  x QSTR
    float* Vs = Ks + 64  * QSTR;      // 64  x QSTR
    float* Ps = Vs + 64  * QSTR;      // 128 x QSTR

    const int tid  = threadIdx.x;
    const int warp = tid >> 5, lane = tid & 31;
    const int g = lane >> 2, tg = lane & 3;
    const int qtile = blockIdx.x, h = blockIdx.y, b = blockIdx.z;
    const int qbase = qtile * 128;
    const int hoff  = h * DKK;

    // load Q tile: 128 rows x 64 cols = 2048 float4, 8 per thread
    #pragma unroll
    for (int i = 0; i < 8; i++) {
        int idx = tid + (i << 8);
        int r = idx >> 4, c = (idx & 15) << 2;
        *(float4*)&Qs[r * QSTR + c] =
            *(const float4*)&Q[((b * SS + qbase + r) * DD) + hoff + c];
    }

    float m0 = -1e30f, m1 = -1e30f, l0 = 0.f, l1 = 0.f;
    float o[8][4];
    #pragma unroll
    for (int ni = 0; ni < 8; ni++)
        #pragma unroll
        for (int r = 0; r < 4; r++) o[ni][r] = 0.f;

    const int pr0 = warp * 16 + g;        // thread's P/O row (and +8)
    const int r0g = qbase + pr0;          // global query row
    const int r1g = r0g + 8;
    const float sscale = 0.125f;          // 1/sqrt(64)
    const int jmax = (qbase + 127) >> 6;  // last kv tile touching this q tile

    for (int j = 0; j <= jmax; j++) {
        __syncthreads();
        const int kvbase = j << 6;
        // load K,V tiles: 64 rows x 64 cols each, 4 float4 per thread per matrix
        #pragma unroll
        for (int i = 0; i < 4; i++) {
            int idx = tid + (i << 8);
            int r = idx >> 4, c = (idx & 15) << 2;
            int grow = (b * SS + kvbase + r) * DD + hoff + c;
            *(float4*)&Ks[r * QSTR + c] = *(const float4*)&Kb[grow];
            *(float4*)&Vs[r * QSTR + c] = *(const float4*)&Vb[grow];
        }
        __syncthreads();

        // warp-level skip: entire warp's rows below this kv tile
        if (kvbase > qbase + warp * 16 + 15) continue;

        // ---- scores = Q Kt ----
        float sc[8][4];
        #pragma unroll
        for (int ni = 0; ni < 8; ni++)
            #pragma unroll
            for (int r = 0; r < 4; r++) sc[ni][r] = 0.f;

        #pragma unroll
        for (int k8 = 0; k8 < 8; k8++) {
            const int kc = (k8 << 3) + tg;
            uint32_t af[4];
            af[0] = f2tf(Qs[pr0 * QSTR + kc]);
            af[1] = f2tf(Qs[(pr0 + 8) * QSTR + kc]);
            af[2] = f2tf(Qs[pr0 * QSTR + kc + 4]);
            af[3] = f2tf(Qs[(pr0 + 8) * QSTR + kc + 4]);
            #pragma unroll
            for (int ni = 0; ni < 8; ni++) {
                uint32_t bf[2];
                int n0 = ni * 8 + g;
                bf[0] = f2tf(Ks[n0 * QSTR + kc]);
                bf[1] = f2tf(Ks[n0 * QSTR + kc + 4]);
                mma8(sc[ni], af, bf);
            }
        }

        // ---- scale + causal mask ----
        const bool need_mask = (kvbase + 63 > qbase + warp * 16);
        if (need_mask) {
            #pragma unroll
            for (int ni = 0; ni < 8; ni++) {
                int c0 = kvbase + ni * 8 + (tg << 1), c1 = c0 + 1;
                sc[ni][0] = (c0 <= r0g) ? sc[ni][0] * sscale : -1e30f;
                sc[ni][1] = (c1 <= r0g) ? sc[ni][1] * sscale : -1e30f;
                sc[ni][2] = (c0 <= r1g) ? sc[ni][2] * sscale : -1e30f;
                sc[ni][3] = (c1 <= r1g) ? sc[ni][3] * sscale : -1e30f;
            }
        } else {
            #pragma unroll
            for (int ni = 0; ni < 8; ni++)
                #pragma unroll
                for (int r = 0; r < 4; r++) sc[ni][r] *= sscale;
        }

        // ---- online softmax (rows pr0 and pr0+8; quad covers all 64 cols) ----
        float t0 = -1e30f, t1 = -1e30f;
        #pragma unroll
        for (int ni = 0; ni < 8; ni++) {
            t0 = fmaxf(t0, fmaxf(sc[ni][0], sc[ni][1]));
            t1 = fmaxf(t1, fmaxf(sc[ni][2], sc[ni][3]));
        }
        t0 = fmaxf(t0, __shfl_xor_sync(0xffffffffu, t0, 1));
        t0 = fmaxf(t0, __shfl_xor_sync(0xffffffffu, t0, 2));
        t1 = fmaxf(t1, __shfl_xor_sync(0xffffffffu, t1, 1));
        t1 = fmaxf(t1, __shfl_xor_sync(0xffffffffu, t1, 2));

        float nm0 = fmaxf(m0, t0), nm1 = fmaxf(m1, t1);
        float cor0 = __expf(m0 - nm0), cor1 = __expf(m1 - nm1);
        float s0 = 0.f, s1 = 0.f;
        #pragma unroll
        for (int ni = 0; ni < 8; ni++) {
            sc[ni][0] = __expf(sc[ni][0] - nm0);
            sc[ni][1] = __expf(sc[ni][1] - nm0);
            sc[ni][2] = __expf(sc[ni][2] - nm1);
            sc[ni][3] = __expf(sc[ni][3] - nm1);
            s0 += sc[ni][0] + sc[ni][1];
            s1 += sc[ni][2] + sc[ni][3];
        }
        s0 += __shfl_xor_sync(0xffffffffu, s0, 1);
        s0 += __shfl_xor_sync(0xffffffffu, s0, 2);
        s1 += __shfl_xor_sync(0xffffffffu, s1, 1);
        s1 += __shfl_xor_sync(0xffffffffu, s1, 2);

        l0 = l0 * cor0 + s0;
        l1 = l1 * cor1 + s1;
        m0 = nm0; m1 = nm1;

        #pragma unroll
        for (int ni = 0; ni < 8; ni++) {
            o[ni][0] *= cor0; o[ni][1] *= cor0;
            o[ni][2] *= cor1; o[ni][3] *= cor1;
        }

        // ---- P to smem (warp-private rows), then O += P V ----
        #pragma unroll
        for (int ni = 0; ni < 8; ni++) {
            int pc = ni * 8 + (tg << 1);
            *(float2*)&Ps[pr0 * QSTR + pc]       = make_float2(sc[ni][0], sc[ni][1]);
            *(float2*)&Ps[(pr0 + 8) * QSTR + pc] = make_float2(sc[ni][2], sc[ni][3]);
        }
        __syncwarp();

        #pragma unroll
        for (int k8 = 0; k8 < 8; k8++) {
            const int kc = (k8 << 3) + tg;
            uint32_t af[4];
            af[0] = f2tf(Ps[pr0 * QSTR + kc]);
            af[1] = f2tf(Ps[(pr0 + 8) * QSTR + kc]);
            af[2] = f2tf(Ps[pr0 * QSTR + kc + 4]);
            af[3] = f2tf(Ps[(pr0 + 8) * QSTR + kc + 4]);
            #pragma unroll
            for (int ni = 0; ni < 8; ni++) {
                uint32_t bf[2];
                int n0 = ni * 8 + g;
                bf[0] = f2tf(Vs[kc * QSTR + n0]);
                bf[1] = f2tf(Vs[(kc + 4) * QSTR + n0]);
                mma8(o[ni], af, bf);
            }
        }
    }

    // epilogue: O /= l, write [B,S,D]
    float inv0 = 1.f / l0, inv1 = 1.f / l1;
    int orow = (b * SS + qbase + pr0) * DD + hoff;
    #pragma unroll
    for (int ni = 0; ni < 8; ni++) {
        int pc = ni * 8 + (tg << 1);
        *(float2*)&O[orow + pc]          = make_float2(o[ni][0] * inv0, o[ni][1] * inv0);
        *(float2*)&O[orow + 8 * DD + pc] = make_float2(o[ni][2] * inv1, o[ni][3] * inv1);
    }
}

// ============================================================================
// launcher
// ============================================================================
#define GEMM_SMEM (2 * 2 * 128 * TSTR * 4)                    // 73728 B
#define ATTN_SMEM ((128 + 64 + 64 + 128) * QSTR * 4)          // 104448 B

extern "C" void kernel_launch(void* const* d_in, const int* in_sizes, int n_in,
                              void* d_out, int out_size)
{
    const float* x  = (const float*)d_in[0];
    const float* Wq = (const float*)d_in[1];
    const float* Wk = (const float*)d_in[2];
    const float* Wv = (const float*)d_in[3];
    const float* Wo = (const float*)d_in[4];
    float* out = (float*)d_out;

    float *qb, *kb, *vb, *ab;
    cudaGetSymbolAddress((void**)&qb, g_qbuf);
    cudaGetSymbolAddress((void**)&kb, g_kbuf);
    cudaGetSymbolAddress((void**)&vb, g_vbuf);
    cudaGetSymbolAddress((void**)&ab, g_abuf);

    cudaFuncSetAttribute(gemm_tf32, cudaFuncAttributeMaxDynamicSharedMemorySize, GEMM_SMEM);
    cudaFuncSetAttribute(attn_kernel, cudaFuncAttributeMaxDynamicSharedMemorySize, ATTN_SMEM);

    dim3 gg(DD / 128, MM / 128);  // (8, 64)
    gemm_tf32<<<gg, 256, GEMM_SMEM>>>(x, Wq, qb, MM, DD, DD);
    gemm_tf32<<<gg, 256, GEMM_SMEM>>>(x, Wk, kb, MM, DD, DD);
    gemm_tf32<<<gg, 256, GEMM_SMEM>>>(x, Wv, vb, MM, DD, DD);

    dim3 ga(SS / 128, HH, BB);    // (16, 16, 4)
    attn_kernel<<<ga, 256, ATTN_SMEM>>>(qb, kb, vb, ab);

    gemm_tf32<<<gg, 256, GEMM_SMEM>>>(ab, Wo, out, MM, DD, DD);
}

// round 5
// speedup vs baseline: 2.3420x; 2.3420x over previous
#include <cuda_runtime.h>
#include <cuda_fp16.h>
#include <cstdint>

// Problem constants
#define BB   4
#define SS   2048
#define DD   1024
#define HH   16
#define DKK  64
#define MM   (BB*SS)          // 8192 rows

// -------- scratch (device globals: no allocation allowed) --------
__device__ __half g_xh [MM*DD];
__device__ __half g_wqh[DD*DD];
__device__ __half g_wkh[DD*DD];
__device__ __half g_wvh[DD*DD];
__device__ __half g_woh[DD*DD];
__device__ __half g_qh [MM*DD];
__device__ __half g_kh [MM*DD];
__device__ __half g_vh [MM*DD];
__device__ __half g_ah [MM*DD];

// -------- helpers --------
__device__ __forceinline__ void mma16(float* c, const uint32_t* a, const uint32_t* b) {
    asm volatile(
        "mma.sync.aligned.m16n8k16.row.col.f32.f16.f16.f32 "
        "{%0,%1,%2,%3}, {%4,%5,%6,%7}, {%8,%9}, {%0,%1,%2,%3};"
        : "+f"(c[0]), "+f"(c[1]), "+f"(c[2]), "+f"(c[3])
        : "r"(a[0]), "r"(a[1]), "r"(a[2]), "r"(a[3]), "r"(b[0]), "r"(b[1]));
}

__device__ __forceinline__ void ldsm4(uint32_t* r, const void* p) {
    uint32_t a = (uint32_t)__cvta_generic_to_shared(p);
    asm volatile("ldmatrix.sync.aligned.m8n8.x4.shared.b16 {%0,%1,%2,%3}, [%4];"
                 : "=r"(r[0]), "=r"(r[1]), "=r"(r[2]), "=r"(r[3]) : "r"(a));
}

__device__ __forceinline__ void ldsm4t(uint32_t* r, const void* p) {
    uint32_t a = (uint32_t)__cvta_generic_to_shared(p);
    asm volatile("ldmatrix.sync.aligned.m8n8.x4.trans.shared.b16 {%0,%1,%2,%3}, [%4];"
                 : "=r"(r[0]), "=r"(r[1]), "=r"(r[2]), "=r"(r[3]) : "r"(a));
}

__device__ __forceinline__ void cp16(void* s, const void* g) {
    uint32_t sa = (uint32_t)__cvta_generic_to_shared(s);
    asm volatile("cp.async.cg.shared.global [%0], [%1], 16;" :: "r"(sa), "l"(g));
}

__device__ __forceinline__ uint32_t packh2(float a, float b) {
    __half2 h = __floats2half2_rn(a, b);
    return *(uint32_t*)&h;
}

// -------- fp32 -> fp16 conversion --------
__global__ void f32_to_f16(const float* __restrict__ in, __half* __restrict__ out, int n) {
    int i = (blockIdx.x * blockDim.x + threadIdx.x) << 2;
    if (i < n) {
        float4 v = *(const float4*)&in[i];
        *(__half2*)&out[i]     = __floats2half2_rn(v.x, v.y);
        *(__half2*)&out[i + 2] = __floats2half2_rn(v.z, v.w);
    }
}

// ============================================================================
// FP16 GEMM: C[M,N] = A[M,K] * B[N,K]^T  (fp32 accum)
// Block 128x128, K-tile 64, 256 threads (8 warps 2x4, warp tile 64x32).
// ldmatrix.x4 operand fetch; padded smem stride (72 halves) => conflict-free.
// ============================================================================
#define GSTR 72   // smem row stride in halves (144B): conflict-free for ldmatrix

template<bool HALF_OUT>
__global__ void __launch_bounds__(256) gemm_f16(
    const __half* __restrict__ A, const __half* __restrict__ Bw,
    void* __restrict__ Cout, int M, int N, int K)
{
    extern __shared__ __half sm[];
    __half* As = sm;                     // [2][128][GSTR]
    __half* Bs = sm + 2 * 128 * GSTR;    // [2][128][GSTR]

    const int tid  = threadIdx.x;
    const int warp = tid >> 5, lane = tid & 31;
    const int wm = (warp >> 2) * 64;
    const int wn = (warp & 3) * 32;
    const int g  = lane >> 2, tg = lane & 3;
    const int bm = blockIdx.y * 128, bn = blockIdx.x * 128;

    // ldmatrix lane->address mappings
    const int arow = (lane & 7) + ((lane & 8) ? 8 : 0);   // A: m-row offset
    const int acol = (lane & 16) ? 8 : 0;                 // A: k offset
    const int brow = (lane & 7) + ((lane & 16) ? 8 : 0);  // B: n-row offset
    const int bcol = (lane & 8) ? 8 : 0;                  // B: k offset

    const __half* Ag = A  + (size_t)bm * K;
    const __half* Bg = Bw + (size_t)bn * K;

    float acc[4][4][4];
    #pragma unroll
    for (int mi = 0; mi < 4; mi++)
        #pragma unroll
        for (int ni = 0; ni < 4; ni++)
            #pragma unroll
            for (int r = 0; r < 4; r++) acc[mi][ni][r] = 0.f;

    const int KT = K >> 6;   // 64-wide k tiles

    // prologue: stage tile 0 (128 rows x 8 16B-chunks each matrix)
    #pragma unroll
    for (int i = 0; i < 4; i++) {
        int idx = tid + (i << 8);
        int r = idx >> 3, c = (idx & 7) << 3;
        cp16(As + r * GSTR + c, Ag + r * K + c);
        cp16(Bs + r * GSTR + c, Bg + r * K + c);
    }
    asm volatile("cp.async.commit_group;");

    for (int kt = 0; kt < KT; kt++) {
        asm volatile("cp.async.wait_group 0;");
        __syncthreads();

        if (kt + 1 < KT) {
            __half* as = As + ((kt + 1) & 1) * 128 * GSTR;
            __half* bs = Bs + ((kt + 1) & 1) * 128 * GSTR;
            const int kk = (kt + 1) << 6;
            #pragma unroll
            for (int i = 0; i < 4; i++) {
                int idx = tid + (i << 8);
                int r = idx >> 3, c = (idx & 7) << 3;
                cp16(as + r * GSTR + c, Ag + r * K + kk + c);
                cp16(bs + r * GSTR + c, Bg + r * K + kk + c);
            }
            asm volatile("cp.async.commit_group;");
        }

        const __half* as = As + (kt & 1) * 128 * GSTR;
        const __half* bs = Bs + (kt & 1) * 128 * GSTR;

        #pragma unroll
        for (int ks = 0; ks < 4; ks++) {
            const int kk = ks << 4;
            uint32_t af[4][4], bf[2][4];
            #pragma unroll
            for (int mi = 0; mi < 4; mi++)
                ldsm4(af[mi], &as[(wm + mi * 16 + arow) * GSTR + kk + acol]);
            #pragma unroll
            for (int nj = 0; nj < 2; nj++)
                ldsm4(bf[nj], &bs[(wn + nj * 16 + brow) * GSTR + kk + bcol]);
            #pragma unroll
            for (int mi = 0; mi < 4; mi++)
                #pragma unroll
                for (int nj = 0; nj < 2; nj++) {
                    mma16(acc[mi][nj * 2],     af[mi], bf[nj]);
                    mma16(acc[mi][nj * 2 + 1], af[mi], bf[nj] + 2);
                }
        }
    }

    // epilogue
    #pragma unroll
    for (int mi = 0; mi < 4; mi++) {
        int row = bm + wm + mi * 16 + g;
        #pragma unroll
        for (int ni = 0; ni < 4; ni++) {
            int col = bn + wn + ni * 8 + (tg << 1);
            if (HALF_OUT) {
                __half* C = (__half*)Cout;
                *(__half2*)&C[(size_t)row * N + col] =
                    __floats2half2_rn(acc[mi][ni][0], acc[mi][ni][1]);
                *(__half2*)&C[(size_t)(row + 8) * N + col] =
                    __floats2half2_rn(acc[mi][ni][2], acc[mi][ni][3]);
            } else {
                float* C = (float*)Cout;
                *(float2*)&C[(size_t)row * N + col] =
                    make_float2(acc[mi][ni][0], acc[mi][ni][1]);
                *(float2*)&C[(size_t)(row + 8) * N + col] =
                    make_float2(acc[mi][ni][2], acc[mi][ni][3]);
            }
        }
    }
}

// ============================================================================
// Causal flash attention, fp16 operands / fp32 softmax+accum.
// Block: one (b, h, 128 Q rows). 8 warps x 16 Q rows. KV tile 64, cp.async
// double-buffered. Q fragments hoisted; P fragments built in-register from
// the QK^T C-fragments (layout identity) -> no P smem round-trip.
// ============================================================================
#define QS2 72   // smem row stride in halves

__global__ void __launch_bounds__(256) attn_kernel(
    const __half* __restrict__ Q, const __half* __restrict__ Kb,
    const __half* __restrict__ Vb, __half* __restrict__ O)
{
    extern __shared__ __half sm[];
    __half* Qs = sm;                       // 128 x QS2
    __half* Ks = Qs + 128 * QS2;           // [2][64][QS2]
    __half* Vs = Ks + 2 * 64 * QS2;        // [2][64][QS2]

    const int tid  = threadIdx.x;
    const int warp = tid >> 5, lane = tid & 31;
    const int g = lane >> 2, tg = lane & 3;
    const int qtile = blockIdx.x, h = blockIdx.y, b = blockIdx.z;
    const int qbase = qtile * 128;
    const int hoff  = h * DKK;

    // ldmatrix lane mappings
    const int arow = (lane & 7) + ((lane & 8) ? 8 : 0);   // A (Q): m-row, k sel
    const int acol = (lane & 16) ? 8 : 0;
    const int brow = (lane & 7) + ((lane & 16) ? 8 : 0);  // B (K): n-row, k sel
    const int bcol = (lane & 8) ? 8 : 0;
    const int vrow = (lane & 7) + ((lane & 8) ? 8 : 0);   // B.trans (V): k-row
    const int vcol = (lane & 16) ? 8 : 0;                 //             n sel

    // ---- stage Q (128x64) and KV tile 0 ----
    #pragma unroll
    for (int i = 0; i < 4; i++) {
        int idx = tid + (i << 8);
        int r = idx >> 3, c = (idx & 7) << 3;
        cp16(Qs + r * QS2 + c, Q + (size_t)((b * SS + qbase + r) * DD) + hoff + c);
    }
    #pragma unroll
    for (int i = 0; i < 4; i++) {
        int idx = tid + (i << 8);
        int mat = idx >> 9, r = (idx >> 3) & 63, c = (idx & 7) << 3;
        const __half* src = Kb;
        __half* dst = Ks;
        if (mat) { src = Vb; dst = Vs; }
        cp16(dst + r * QS2 + c, src + (size_t)((b * SS + r) * DD) + hoff + c);
    }
    asm volatile("cp.async.commit_group;");
    asm volatile("cp.async.wait_group 0;");
    __syncthreads();

    // ---- hoist Q fragments (4 k-steps of 16) ----
    uint32_t qf[4][4];
    #pragma unroll
    for (int ks = 0; ks < 4; ks++)
        ldsm4(qf[ks], &Qs[(warp * 16 + arow) * QS2 + (ks << 4) + acol]);

    float m0 = -1e30f, m1 = -1e30f, l0 = 0.f, l1 = 0.f;
    float o[8][4];
    #pragma unroll
    for (int ni = 0; ni < 8; ni++)
        #pragma unroll
        for (int r = 0; r < 4; r++) o[ni][r] = 0.f;

    const int pr0 = warp * 16 + g;
    const int r0g = qbase + pr0;
    const int r1g = r0g + 8;
    const float sscale = 0.125f;          // 1/sqrt(64)
    const int jmax = (qbase + 127) >> 6;

    for (int j = 0; j <= jmax; j++) {
        const int kvbase = j << 6;
        const int cur = j & 1;

        // prefetch next KV tile into the other buffer
        if (j + 1 <= jmax) {
            const int nb = (j + 1) & 1;
            const int nkv = (j + 1) << 6;
            #pragma unroll
            for (int i = 0; i < 4; i++) {
                int idx = tid + (i << 8);
                int mat = idx >> 9, r = (idx >> 3) & 63, c = (idx & 7) << 3;
                const __half* src = Kb;
                __half* dst = Ks + nb * 64 * QS2;
                if (mat) { src = Vb; dst = Vs + nb * 64 * QS2; }
                cp16(dst + r * QS2 + c, src + (size_t)((b * SS + nkv + r) * DD) + hoff + c);
            }
            asm volatile("cp.async.commit_group;");
        }

        // warp-level skip: entire warp's rows below this kv tile
        if (kvbase <= qbase + warp * 16 + 15) {
            const __half* ks_ = Ks + cur * 64 * QS2;
            const __half* vs_ = Vs + cur * 64 * QS2;

            // ---- scores = Q K^T ----
            float sc[8][4];
            #pragma unroll
            for (int ni = 0; ni < 8; ni++)
                #pragma unroll
                for (int r = 0; r < 4; r++) sc[ni][r] = 0.f;

            #pragma unroll
            for (int ks = 0; ks < 4; ks++) {
                const int kk = ks << 4;
                #pragma unroll
                for (int nj = 0; nj < 4; nj++) {
                    uint32_t kf[4];
                    ldsm4(kf, &ks_[(nj * 16 + brow) * QS2 + kk + bcol]);
                    mma16(sc[nj * 2],     qf[ks], kf);
                    mma16(sc[nj * 2 + 1], qf[ks], kf + 2);
                }
            }

            // ---- scale + causal mask ----
            const bool need_mask = (kvbase + 63 > qbase + warp * 16);
            if (need_mask) {
                #pragma unroll
                for (int ni = 0; ni < 8; ni++) {
                    int c0 = kvbase + ni * 8 + (tg << 1), c1 = c0 + 1;
                    sc[ni][0] = (c0 <= r0g) ? sc[ni][0] * sscale : -1e30f;
                    sc[ni][1] = (c1 <= r0g) ? sc[ni][1] * sscale : -1e30f;
                    sc[ni][2] = (c0 <= r1g) ? sc[ni][2] * sscale : -1e30f;
                    sc[ni][3] = (c1 <= r1g) ? sc[ni][3] * sscale : -1e30f;
                }
            } else {
                #pragma unroll
                for (int ni = 0; ni < 8; ni++)
                    #pragma unroll
                    for (int r = 0; r < 4; r++) sc[ni][r] *= sscale;
            }

            // ---- online softmax (quad shuffles) ----
            float t0 = -1e30f, t1 = -1e30f;
            #pragma unroll
            for (int ni = 0; ni < 8; ni++) {
                t0 = fmaxf(t0, fmaxf(sc[ni][0], sc[ni][1]));
                t1 = fmaxf(t1, fmaxf(sc[ni][2], sc[ni][3]));
            }
            t0 = fmaxf(t0, __shfl_xor_sync(0xffffffffu, t0, 1));
            t0 = fmaxf(t0, __shfl_xor_sync(0xffffffffu, t0, 2));
            t1 = fmaxf(t1, __shfl_xor_sync(0xffffffffu, t1, 1));
            t1 = fmaxf(t1, __shfl_xor_sync(0xffffffffu, t1, 2));

            float nm0 = fmaxf(m0, t0), nm1 = fmaxf(m1, t1);
            float cor0 = __expf(m0 - nm0), cor1 = __expf(m1 - nm1);
            float s0 = 0.f, s1 = 0.f;
            #pragma unroll
            for (int ni = 0; ni < 8; ni++) {
                sc[ni][0] = __expf(sc[ni][0] - nm0);
                sc[ni][1] = __expf(sc[ni][1] - nm0);
                sc[ni][2] = __expf(sc[ni][2] - nm1);
                sc[ni][3] = __expf(sc[ni][3] - nm1);
                s0 += sc[ni][0] + sc[ni][1];
                s1 += sc[ni][2] + sc[ni][3];
            }
            s0 += __shfl_xor_sync(0xffffffffu, s0, 1);
            s0 += __shfl_xor_sync(0xffffffffu, s0, 2);
            s1 += __shfl_xor_sync(0xffffffffu, s1, 1);
            s1 += __shfl_xor_sync(0xffffffffu, s1, 2);

            l0 = l0 * cor0 + s0;
            l1 = l1 * cor1 + s1;
            m0 = nm0; m1 = nm1;

            #pragma unroll
            for (int ni = 0; ni < 8; ni++) {
                o[ni][0] *= cor0; o[ni][1] *= cor0;
                o[ni][2] *= cor1; o[ni][3] *= cor1;
            }

            // ---- O += P V  (P frags packed straight from C-frag layout) ----
            #pragma unroll
            for (int ks = 0; ks < 4; ks++) {
                uint32_t pa[4];
                pa[0] = packh2(sc[2 * ks][0],     sc[2 * ks][1]);
                pa[1] = packh2(sc[2 * ks][2],     sc[2 * ks][3]);
                pa[2] = packh2(sc[2 * ks + 1][0], sc[2 * ks + 1][1]);
                pa[3] = packh2(sc[2 * ks + 1][2], sc[2 * ks + 1][3]);
                #pragma unroll
                for (int nj = 0; nj < 4; nj++) {
                    uint32_t vf[4];
                    ldsm4t(vf, &vs_[((ks << 4) + vrow) * QS2 + nj * 16 + vcol]);
                    mma16(o[nj * 2],     pa, vf);
                    mma16(o[nj * 2 + 1], pa, vf + 2);
                }
            }
        }

        if (j + 1 <= jmax) {
            asm volatile("cp.async.wait_group 0;");
            __syncthreads();
        }
    }

    // epilogue: O /= l, write fp16 [B,S,D]
    float inv0 = 1.f / l0, inv1 = 1.f / l1;
    size_t orow = (size_t)((b * SS + qbase + pr0) * DD) + hoff;
    #pragma unroll
    for (int ni = 0; ni < 8; ni++) {
        int pc = ni * 8 + (tg << 1);
        *(__half2*)&O[orow + pc] =
            __floats2half2_rn(o[ni][0] * inv0, o[ni][1] * inv0);
        *(__half2*)&O[orow + 8 * DD + pc] =
            __floats2half2_rn(o[ni][2] * inv1, o[ni][3] * inv1);
    }
}

// ============================================================================
// launcher
// ============================================================================
#define GEMM_SMEM (2 * 2 * 128 * GSTR * 2)                     // 73728 B
#define ATTN_SMEM ((128 + 2 * 64 + 2 * 64) * QS2 * 2)          // 55296 B

extern "C" void kernel_launch(void* const* d_in, const int* in_sizes, int n_in,
                              void* d_out, int out_size)
{
    const float* x  = (const float*)d_in[0];
    const float* Wq = (const float*)d_in[1];
    const float* Wk = (const float*)d_in[2];
    const float* Wv = (const float*)d_in[3];
    const float* Wo = (const float*)d_in[4];
    float* out = (float*)d_out;

    __half *xh, *wqh, *wkh, *wvh, *woh, *qh, *kh, *vh, *ah;
    cudaGetSymbolAddress((void**)&xh,  g_xh);
    cudaGetSymbolAddress((void**)&wqh, g_wqh);
    cudaGetSymbolAddress((void**)&wkh, g_wkh);
    cudaGetSymbolAddress((void**)&wvh, g_wvh);
    cudaGetSymbolAddress((void**)&woh, g_woh);
    cudaGetSymbolAddress((void**)&qh,  g_qh);
    cudaGetSymbolAddress((void**)&kh,  g_kh);
    cudaGetSymbolAddress((void**)&vh,  g_vh);
    cudaGetSymbolAddress((void**)&ah,  g_ah);

    cudaFuncSetAttribute(gemm_f16<true>,  cudaFuncAttributeMaxDynamicSharedMemorySize, GEMM_SMEM);
    cudaFuncSetAttribute(gemm_f16<false>, cudaFuncAttributeMaxDynamicSharedMemorySize, GEMM_SMEM);
    cudaFuncSetAttribute(attn_kernel,     cudaFuncAttributeMaxDynamicSharedMemorySize, ATTN_SMEM);

    // fp32 -> fp16 conversions
    const int NX = MM * DD, NW = DD * DD;
    f32_to_f16<<<(NX / 4 + 255) / 256, 256>>>(x,  xh,  NX);
    f32_to_f16<<<(NW / 4 + 255) / 256, 256>>>(Wq, wqh, NW);
    f32_to_f16<<<(NW / 4 + 255) / 256, 256>>>(Wk, wkh, NW);
    f32_to_f16<<<(NW / 4 + 255) / 256, 256>>>(Wv, wvh, NW);
    f32_to_f16<<<(NW / 4 + 255) / 256, 256>>>(Wo, woh, NW);

    dim3 gg(DD / 128, MM / 128);  // (8, 64)
    gemm_f16<true><<<gg, 256, GEMM_SMEM>>>(xh, wqh, qh, MM, DD, DD);
    gemm_f16<true><<<gg, 256, GEMM_SMEM>>>(xh, wkh, kh, MM, DD, DD);
    gemm_f16<true><<<gg, 256, GEMM_SMEM>>>(xh, wvh, vh, MM, DD, DD);

    dim3 ga(SS / 128, HH, BB);    // (16, 16, 4)
    attn_kernel<<<ga, 256, ATTN_SMEM>>>(qh, kh, vh, ah);

    gemm_f16<false><<<gg, 256, GEMM_SMEM>>>(ah, woh, out, MM, DD, DD);
}